// round 1
// baseline (speedup 1.0000x reference)
#include <cuda_runtime.h>
#include <math.h>

// EMD approxmatch (Fan et al.) on GB300.
// Shapes: xyz1, xyz2 = (B=4, 3, N=4096) float32. Output: scalar float32.
//
// Per sweep (10 sweeps, levels -4^7..-4^0, -0.25, 0):
//   P1: suml_i = sum_j ex2(klg*dist + log2(remainR_j))      -> lgL_i = log2(remainL_i/(EPS+suml_i))
//   P2: raw_j  = sum_i ex2(klg*dist + lgL_i)                -> ratioR_j, remainR_j update, lgR_j
//   P3: w_ij   = ex2(klg*dist + lgL_i + lgR_j); remainL_i -= sum_j w; cost += w*sqrt(dist)
// klg = level*log2(e); dist recomputed from points each pass (compute-bound, MUFU.EX2 floor).

#define EMD_EPS 1e-9f
#define MAXBN (4 * 4096)
#define ROWS_PER_BLOCK 16
#define TILE 2048

__device__ float4 g_p1[MAXBN];   // (x,y,z,|p|^2) for xyz1
__device__ float4 g_p2[MAXBN];   // (x,y,z,|p|^2) for xyz2
__device__ float  g_rL[MAXBN];   // remainL
__device__ float  g_rR[MAXBN];   // remainR
__device__ float  g_lgL[MAXBN];  // log2(ratioL)
__device__ float  g_lgR[MAXBN];  // log2(ratioR)
__device__ float  g_cost;        // sum over batches of sum(match * d)

__device__ __forceinline__ float ex2f(float x) {
    float y; asm("ex2.approx.ftz.f32 %0, %1;" : "=f"(y) : "f"(x)); return y;
}
__device__ __forceinline__ float lg2f(float x) {
    float y; asm("lg2.approx.ftz.f32 %0, %1;" : "=f"(y) : "f"(x)); return y;
}
__device__ __forceinline__ float sqrtf_apx(float x) {
    float y; asm("sqrt.approx.ftz.f32 %0, %1;" : "=f"(y) : "f"(x)); return y;
}

__global__ void setup_kernel(const float* __restrict__ x1, const float* __restrict__ x2,
                             float multiL, float multiR, int N, int total) {
    int idx = blockIdx.x * blockDim.x + threadIdx.x;
    if (idx >= total) return;
    int b = idx / N, i = idx - b * N;
    const float* p1 = x1 + (size_t)b * 3 * N + i;
    const float* p2 = x2 + (size_t)b * 3 * N + i;
    float a0 = p1[0], a1 = p1[N], a2 = p1[2 * N];
    g_p1[idx] = make_float4(a0, a1, a2, a0 * a0 + a1 * a1 + a2 * a2);
    float b0 = p2[0], b1 = p2[N], b2 = p2[2 * N];
    g_p2[idx] = make_float4(b0, b1, b2, b0 * b0 + b1 * b1 + b2 * b2);
    g_rL[idx] = multiL;
    g_rR[idx] = multiR;
    if (idx == 0) g_cost = 0.0f;
}

// MODE 1: rows = x1 points, cols = x2 points, fold = log2(remainR); epilogue writes lgL.
// MODE 2: rows = x2 points, cols = x1 points, fold = lgL;           epilogue updates remainR, writes lgR.
template <int MODE>
__global__ void __launch_bounds__(256) pass12_kernel(float klg, float c2, int N) {
    __shared__ float4 sq[TILE];
    const int b    = blockIdx.y;
    const int base = b * N;
    const int t    = threadIdx.x;
    const int warp = t >> 5, lane = t & 31;
    const int r0   = blockIdx.x * ROWS_PER_BLOCK + warp * 2;

    const float4* P = (MODE == 1) ? g_p1 : g_p2;
    const float4* Q = (MODE == 1) ? g_p2 : g_p1;

    float4 A = P[base + r0];
    float4 Bv = P[base + r0 + 1];
    float px0 = c2 * A.x,  py0 = c2 * A.y,  pz0 = c2 * A.z,  w0 = klg * A.w;
    float px1 = c2 * Bv.x, py1 = c2 * Bv.y, pz1 = c2 * Bv.z, w1 = klg * Bv.w;
    float acc0 = 0.0f, acc1 = 0.0f;

    for (int c = 0; c < N; c += TILE) {
#pragma unroll
        for (int k = 0; k < TILE / 256; k++) {
            int jj = t + k * 256;
            int j  = base + c + jj;
            float4 q = Q[j];
            float f;
            if (MODE == 1) f = fmaf(klg, q.w, lg2f(g_rR[j]));
            else           f = fmaf(klg, q.w, g_lgL[j]);
            sq[jj] = make_float4(q.x, q.y, q.z, f);
        }
        __syncthreads();
#pragma unroll 4
        for (int jj = 0; jj < TILE / 32; jj++) {
            float4 q = sq[jj * 32 + lane];
            float t0 = fmaf(px0, q.x, q.w);
            float t1 = fmaf(py0, q.y, w0);
            acc0 += ex2f(fmaf(pz0, q.z, t0 + t1));
            float u0 = fmaf(px1, q.x, q.w);
            float u1 = fmaf(py1, q.y, w1);
            acc1 += ex2f(fmaf(pz1, q.z, u0 + u1));
        }
        __syncthreads();
    }

#pragma unroll
    for (int off = 16; off; off >>= 1) {
        acc0 += __shfl_down_sync(0xffffffffu, acc0, off);
        acc1 += __shfl_down_sync(0xffffffffu, acc1, off);
    }

    if (lane == 0) {
        if (MODE == 1) {
            g_lgL[base + r0]     = lg2f(g_rL[base + r0]     / (EMD_EPS + acc0));
            g_lgL[base + r0 + 1] = lg2f(g_rL[base + r0 + 1] / (EMD_EPS + acc1));
        } else {
            {
                float rr = g_rR[base + r0];
                float sumr = rr * acc0;
                float cons = fminf(rr / (sumr + EMD_EPS), 1.0f);
                g_lgR[base + r0] = lg2f(cons * rr);
                g_rR[base + r0]  = fmaxf(0.0f, rr - sumr);
            }
            {
                float rr = g_rR[base + r0 + 1];
                float sumr = rr * acc1;
                float cons = fminf(rr / (sumr + EMD_EPS), 1.0f);
                g_lgR[base + r0 + 1] = lg2f(cons * rr);
                g_rR[base + r0 + 1]  = fmaxf(0.0f, rr - sumr);
            }
        }
    }
}

__global__ void __launch_bounds__(256) pass3_kernel(float klg, int N) {
    __shared__ float4 sq[TILE];
    __shared__ float  sl[TILE];
    const int b    = blockIdx.y;
    const int base = b * N;
    const int t    = threadIdx.x;
    const int warp = t >> 5, lane = t & 31;
    const int r0   = blockIdx.x * ROWS_PER_BLOCK + warp * 2;

    float4 A  = g_p1[base + r0];
    float4 Bv = g_p1[base + r0 + 1];
    float lg0 = g_lgL[base + r0];
    float lg1 = g_lgL[base + r0 + 1];
    float wa0 = 0.0f, wa1 = 0.0f, cost = 0.0f;

    for (int c = 0; c < N; c += TILE) {
#pragma unroll
        for (int k = 0; k < TILE / 256; k++) {
            int jj = t + k * 256;
            int j  = base + c + jj;
            sq[jj] = g_p2[j];
            sl[jj] = g_lgR[j];
        }
        __syncthreads();
#pragma unroll 4
        for (int jj = 0; jj < TILE / 32; jj++) {
            float4 q = sq[jj * 32 + lane];
            float lq = sl[jj * 32 + lane];
            // row 0
            {
                float cr   = fmaf(A.z, q.z, fmaf(A.y, q.y, A.x * q.x));
                float dist = fmaf(-2.0f, cr, A.w + q.w);
                float dc   = fmaxf(dist, 1e-20f);
                float wv   = ex2f(fmaf(klg, dc, lg0 + lq));
                wa0 += wv;
                cost = fmaf(wv, sqrtf_apx(dc), cost);
            }
            // row 1
            {
                float cr   = fmaf(Bv.z, q.z, fmaf(Bv.y, q.y, Bv.x * q.x));
                float dist = fmaf(-2.0f, cr, Bv.w + q.w);
                float dc   = fmaxf(dist, 1e-20f);
                float wv   = ex2f(fmaf(klg, dc, lg1 + lq));
                wa1 += wv;
                cost = fmaf(wv, sqrtf_apx(dc), cost);
            }
        }
        __syncthreads();
    }

#pragma unroll
    for (int off = 16; off; off >>= 1) {
        wa0  += __shfl_down_sync(0xffffffffu, wa0, off);
        wa1  += __shfl_down_sync(0xffffffffu, wa1, off);
        cost += __shfl_down_sync(0xffffffffu, cost, off);
    }
    if (lane == 0) {
        g_rL[base + r0]     = fmaxf(0.0f, g_rL[base + r0]     - wa0);
        g_rL[base + r0 + 1] = fmaxf(0.0f, g_rL[base + r0 + 1] - wa1);
        atomicAdd(&g_cost, cost);
    }
}

__global__ void final_kernel(float* out, float inv) {
    out[0] = g_cost * inv;
}

extern "C" void kernel_launch(void* const* d_in, const int* in_sizes, int n_in,
                              void* d_out, int out_size) {
    const float* x1 = (const float*)d_in[0];
    const float* x2 = (const float*)d_in[1];
    const int B = 4;
    const int N = in_sizes[0] / (3 * B);   // 4096
    const int n = N, m = N;

    float multiL, multiR;
    if (n >= m) { multiL = 1.0f; multiR = (float)(n / m); }
    else        { multiL = (float)(m / n); multiR = 1.0f; }

    int total = B * N;
    setup_kernel<<<(total + 255) / 256, 256>>>(x1, x2, multiL, multiR, N, total);

    dim3 grid(N / ROWS_PER_BLOCK, B);
    const float LOG2E = 1.4426950408889634f;
    for (int s = 0; s < 10; s++) {
        float level = (s < 9) ? -ldexpf(1.0f, 2 * (7 - s)) : 0.0f;  // -4^(7-s), then 0
        float klg = level * LOG2E;
        float c2  = -2.0f * klg;
        pass12_kernel<1><<<grid, 256>>>(klg, c2, N);
        pass12_kernel<2><<<grid, 256>>>(klg, c2, N);
        pass3_kernel<<<grid, 256>>>(klg, N);
    }

    float mn = (float)((n < m ? n : m) * B);
    final_kernel<<<1, 1>>>((float*)d_out, 1.0f / mn);
}

// round 2
// speedup vs baseline: 1.1452x; 1.1452x over previous
#include <cuda_runtime.h>
#include <math.h>

// EMD approxmatch (Fan et al.) on GB300 — round 2: f32x2 packed FMA, 4 rows/thread,
// MUFU-floor targeted. B=4, N=4096.
//
// Per sweep (10 sweeps, levels -4^7..-4^0, -0.25, 0):
//   P1: suml_i = sum_j ex2(klg*dist + log2(remainR_j))      -> lgL_i = log2(remainL_i/(EPS+suml_i))
//   P2: raw_j  = sum_i ex2(klg*dist + lgL_i)                -> ratioR_j, remainR_j update, lgR_j
//   P3: w_ij   = ex2(klg*dist + lq_j) * ex2(lgL_i); remainL_i -= sum_j w; cost += w*sqrt(dist)

#define EMD_EPS 1e-9f
#define MAXBN (4 * 4096)
#define TILE 1024
#define ROWS_PER_BLOCK 16   // 4 warps x 4 rows

typedef unsigned long long u64;

__device__ float4 g_p1[MAXBN];   // (x,y,z,|p|^2) xyz1
__device__ float4 g_p2[MAXBN];   // (x,y,z,|p|^2) xyz2
__device__ float  g_rL[MAXBN];
__device__ float  g_rR[MAXBN];
__device__ float  g_lgL[MAXBN];  // log2(ratioL)
__device__ float  g_lgR[MAXBN];  // log2(ratioR)
__device__ float  g_cost;

__device__ __forceinline__ float ex2f(float x) {
    float y; asm("ex2.approx.ftz.f32 %0, %1;" : "=f"(y) : "f"(x)); return y;
}
__device__ __forceinline__ float lg2f(float x) {
    float y; asm("lg2.approx.ftz.f32 %0, %1;" : "=f"(y) : "f"(x)); return y;
}
__device__ __forceinline__ float sqrtf_apx(float x) {
    float y; asm("sqrt.approx.ftz.f32 %0, %1;" : "=f"(y) : "f"(x)); return y;
}

// ---- packed f32x2 helpers (sm_103a) ----
__device__ __forceinline__ u64 pk2(float a, float b) {
    u64 r; asm("mov.b64 %0, {%1, %2};" : "=l"(r) : "f"(a), "f"(b)); return r;
}
__device__ __forceinline__ void upk2(float& a, float& b, u64 v) {
    asm("mov.b64 {%0, %1}, %2;" : "=f"(a), "=f"(b) : "l"(v));
}
__device__ __forceinline__ u64 f2fma(u64 a, u64 b, u64 c) {
    u64 d; asm("fma.rn.f32x2 %0, %1, %2, %3;" : "=l"(d) : "l"(a), "l"(b), "l"(c)); return d;
}
__device__ __forceinline__ u64 f2add(u64 a, u64 b) {
    u64 d; asm("add.rn.f32x2 %0, %1, %2;" : "=l"(d) : "l"(a), "l"(b)); return d;
}
__device__ __forceinline__ u64 f2mul(u64 a, u64 b) {
    u64 d; asm("mul.rn.f32x2 %0, %1, %2;" : "=l"(d) : "l"(a), "l"(b)); return d;
}

__global__ void setup_kernel(const float* __restrict__ x1, const float* __restrict__ x2,
                             float multiL, float multiR, int N, int total) {
    int idx = blockIdx.x * blockDim.x + threadIdx.x;
    if (idx >= total) return;
    int b = idx / N, i = idx - b * N;
    const float* p1 = x1 + (size_t)b * 3 * N + i;
    const float* p2 = x2 + (size_t)b * 3 * N + i;
    float a0 = p1[0], a1 = p1[N], a2 = p1[2 * N];
    g_p1[idx] = make_float4(a0, a1, a2, a0 * a0 + a1 * a1 + a2 * a2);
    float b0 = p2[0], b1 = p2[N], b2 = p2[2 * N];
    g_p2[idx] = make_float4(b0, b1, b2, b0 * b0 + b1 * b1 + b2 * b2);
    g_rL[idx] = multiL;
    g_rR[idx] = multiR;
    if (idx == 0) g_cost = 0.0f;
}

// MODE 1: rows = x1, cols = x2, fold = log2(remainR_j); epilogue writes lgL.
// MODE 2: rows = x2, cols = x1, fold = lgL_j;           epilogue updates remainR, writes lgR.
template <int MODE>
__global__ void __launch_bounds__(128, 8) pass12_kernel(float klg, float c2, int N) {
    __shared__ float4 sq[TILE];
    const int b    = blockIdx.y;
    const int base = b * N;
    const int t    = threadIdx.x;
    const int warp = t >> 5, lane = t & 31;
    const int r0   = blockIdx.x * ROWS_PER_BLOCK + warp * 4;

    const float4* P = (MODE == 1) ? g_p1 : g_p2;
    const float4* Q = (MODE == 1) ? g_p2 : g_p1;

    float4 A0 = P[base + r0], A1 = P[base + r0 + 1];
    float4 A2 = P[base + r0 + 2], A3 = P[base + r0 + 3];
    u64 px01 = pk2(c2 * A0.x, c2 * A1.x), px23 = pk2(c2 * A2.x, c2 * A3.x);
    u64 py01 = pk2(c2 * A0.y, c2 * A1.y), py23 = pk2(c2 * A2.y, c2 * A3.y);
    u64 pz01 = pk2(c2 * A0.z, c2 * A1.z), pz23 = pk2(c2 * A2.z, c2 * A3.z);
    u64 w01  = pk2(klg * A0.w, klg * A1.w), w23 = pk2(klg * A2.w, klg * A3.w);
    u64 acc01 = 0ull, acc23 = 0ull;   // packed {0.0f, 0.0f}

    for (int c = 0; c < N; c += TILE) {
#pragma unroll
        for (int k = 0; k < TILE / 128; k++) {
            int jj = t + k * 128;
            int j  = base + c + jj;
            float4 q = Q[j];
            float f;
            if (MODE == 1) f = fmaf(klg, q.w, lg2f(g_rR[j]));
            else           f = fmaf(klg, q.w, g_lgL[j]);
            sq[jj] = make_float4(q.x, q.y, q.z, f);
        }
        __syncthreads();
#pragma unroll 8
        for (int jj = 0; jj < TILE / 32; jj++) {
            float4 q = sq[jj * 32 + lane];
            u64 qx2 = pk2(q.x, q.x), qy2 = pk2(q.y, q.y);
            u64 qz2 = pk2(q.z, q.z), f2  = pk2(q.w, q.w);
            u64 a01 = f2fma(pz01, qz2, f2fma(py01, qy2, f2fma(px01, qx2, f2add(f2, w01))));
            u64 a23 = f2fma(pz23, qz2, f2fma(py23, qy2, f2fma(px23, qx2, f2add(f2, w23))));
            float e0, e1, e2, e3;
            upk2(e0, e1, a01); upk2(e2, e3, a23);
            acc01 = f2add(acc01, pk2(ex2f(e0), ex2f(e1)));
            acc23 = f2add(acc23, pk2(ex2f(e2), ex2f(e3)));
        }
        __syncthreads();
    }

#pragma unroll
    for (int off = 16; off; off >>= 1) {
        acc01 = f2add(acc01, __shfl_down_sync(0xffffffffu, acc01, off));
        acc23 = f2add(acc23, __shfl_down_sync(0xffffffffu, acc23, off));
    }

    if (lane == 0) {
        float a[4];
        upk2(a[0], a[1], acc01); upk2(a[2], a[3], acc23);
#pragma unroll
        for (int i = 0; i < 4; i++) {
            int r = base + r0 + i;
            if (MODE == 1) {
                g_lgL[r] = lg2f(g_rL[r] / (EMD_EPS + a[i]));
            } else {
                float rr   = g_rR[r];
                float sumr = rr * a[i];
                float cons = fminf(rr / (sumr + EMD_EPS), 1.0f);
                g_lgR[r] = lg2f(cons * rr);
                g_rR[r]  = fmaxf(0.0f, rr - sumr);
            }
        }
    }
}

__global__ void __launch_bounds__(128, 8) pass3_kernel(float klg, int N) {
    __shared__ float4 sq[TILE];
    __shared__ float  sl[TILE];
    const int b    = blockIdx.y;
    const int base = b * N;
    const int t    = threadIdx.x;
    const int warp = t >> 5, lane = t & 31;
    const int r0   = blockIdx.x * ROWS_PER_BLOCK + warp * 4;

    float4 A0 = g_p1[base + r0], A1 = g_p1[base + r0 + 1];
    float4 A2 = g_p1[base + r0 + 2], A3 = g_p1[base + r0 + 3];
    // pre-scaled coords: cr2m = -2 * (a . q)
    u64 ax01 = pk2(-2.0f * A0.x, -2.0f * A1.x), ax23 = pk2(-2.0f * A2.x, -2.0f * A3.x);
    u64 ay01 = pk2(-2.0f * A0.y, -2.0f * A1.y), ay23 = pk2(-2.0f * A2.y, -2.0f * A3.y);
    u64 az01 = pk2(-2.0f * A0.z, -2.0f * A1.z), az23 = pk2(-2.0f * A2.z, -2.0f * A3.z);
    u64 aw01 = pk2(A0.w, A1.w), aw23 = pk2(A2.w, A3.w);
    u64 klg2 = pk2(klg, klg);
    u64 wa01 = 0ull, wa23 = 0ull, cs01 = 0ull, cs23 = 0ull;

    for (int c = 0; c < N; c += TILE) {
#pragma unroll
        for (int k = 0; k < TILE / 128; k++) {
            int jj = t + k * 128;
            int j  = base + c + jj;
            sq[jj] = g_p2[j];
            sl[jj] = g_lgR[j];
        }
        __syncthreads();
#pragma unroll 4
        for (int jj = 0; jj < TILE / 32; jj++) {
            float4 q = sq[jj * 32 + lane];
            float lq = sl[jj * 32 + lane];
            u64 qx2 = pk2(q.x, q.x), qy2 = pk2(q.y, q.y);
            u64 qz2 = pk2(q.z, q.z), qw2 = pk2(q.w, q.w);
            u64 lq2 = pk2(lq, lq);
            // pair 0/1
            {
                u64 cr2  = f2fma(az01, qz2, f2fma(ay01, qy2, f2mul(ax01, qx2)));
                u64 di2  = f2add(cr2, f2add(aw01, qw2));
                float d0, d1; upk2(d0, d1, di2);
                float c0 = fmaxf(d0, 1e-20f), c1 = fmaxf(d1, 1e-20f);
                u64 ar2  = f2fma(klg2, pk2(c0, c1), lq2);
                float a0, a1; upk2(a0, a1, ar2);
                float w0 = ex2f(a0), w1 = ex2f(a1);
                float s0 = sqrtf_apx(c0), s1 = sqrtf_apx(c1);
                u64 wv2 = pk2(w0, w1);
                wa01 = f2add(wa01, wv2);
                cs01 = f2fma(wv2, pk2(s0, s1), cs01);
            }
            // pair 2/3
            {
                u64 cr2  = f2fma(az23, qz2, f2fma(ay23, qy2, f2mul(ax23, qx2)));
                u64 di2  = f2add(cr2, f2add(aw23, qw2));
                float d0, d1; upk2(d0, d1, di2);
                float c0 = fmaxf(d0, 1e-20f), c1 = fmaxf(d1, 1e-20f);
                u64 ar2  = f2fma(klg2, pk2(c0, c1), lq2);
                float a0, a1; upk2(a0, a1, ar2);
                float w0 = ex2f(a0), w1 = ex2f(a1);
                float s0 = sqrtf_apx(c0), s1 = sqrtf_apx(c1);
                u64 wv2 = pk2(w0, w1);
                wa23 = f2add(wa23, wv2);
                cs23 = f2fma(wv2, pk2(s0, s1), cs23);
            }
        }
        __syncthreads();
    }

#pragma unroll
    for (int off = 16; off; off >>= 1) {
        wa01 = f2add(wa01, __shfl_down_sync(0xffffffffu, wa01, off));
        wa23 = f2add(wa23, __shfl_down_sync(0xffffffffu, wa23, off));
        cs01 = f2add(cs01, __shfl_down_sync(0xffffffffu, cs01, off));
        cs23 = f2add(cs23, __shfl_down_sync(0xffffffffu, cs23, off));
    }

    if (lane == 0) {
        float wa[4], cs[4];
        upk2(wa[0], wa[1], wa01); upk2(wa[2], wa[3], wa23);
        upk2(cs[0], cs[1], cs01); upk2(cs[2], cs[3], cs23);
        float cost = 0.0f;
#pragma unroll
        for (int i = 0; i < 4; i++) {
            int r = base + r0 + i;
            float eL = ex2f(g_lgL[r]);          // = ratioL_r (<= ~1e9, no overflow)
            g_rL[r] = fmaxf(0.0f, g_rL[r] - eL * wa[i]);
            cost = fmaf(eL, cs[i], cost);
        }
        atomicAdd(&g_cost, cost);
    }
}

__global__ void final_kernel(float* out, float inv) {
    out[0] = g_cost * inv;
}

extern "C" void kernel_launch(void* const* d_in, const int* in_sizes, int n_in,
                              void* d_out, int out_size) {
    const float* x1 = (const float*)d_in[0];
    const float* x2 = (const float*)d_in[1];
    const int B = 4;
    const int N = in_sizes[0] / (3 * B);   // 4096
    const int n = N, m = N;

    float multiL, multiR;
    if (n >= m) { multiL = 1.0f; multiR = (float)(n / m); }
    else        { multiL = (float)(m / n); multiR = 1.0f; }

    int total = B * N;
    setup_kernel<<<(total + 255) / 256, 256>>>(x1, x2, multiL, multiR, N, total);

    dim3 grid(N / ROWS_PER_BLOCK, B);
    const float LOG2E = 1.4426950408889634f;
    for (int s = 0; s < 10; s++) {
        float level = (s < 9) ? -ldexpf(1.0f, 2 * (7 - s)) : 0.0f;  // -4^(7-s), then 0
        float klg = level * LOG2E;
        float c2  = -2.0f * klg;
        pass12_kernel<1><<<grid, 128>>>(klg, c2, N);
        pass12_kernel<2><<<grid, 128>>>(klg, c2, N);
        pass3_kernel<<<grid, 128>>>(klg, N);
    }

    float mn = (float)((n < m ? n : m) * B);
    final_kernel<<<1, 1>>>((float*)d_out, 1.0f / mn);
}

// round 3
// speedup vs baseline: 1.2542x; 1.0952x over previous
#include <cuda_runtime.h>
#include <math.h>

// EMD approxmatch (Fan et al.) on GB300 — round 3.
// Packed-column f32x2 layout, underflow-skip sparse sweeps, exact level-0 sweep.
// B=4, N=4096. 10 sweeps, levels -4^7..-4^0, -0.25, 0.

#define EMD_EPS 1e-9f
#define MAXBN (4 * 4096)
#define TILE 1024
#define ROWS_PER_BLOCK 16   // 4 warps x 4 rows/warp

typedef unsigned long long u64;

__device__ float4 g_p1[MAXBN];   // (x,y,z,|p|^2) xyz1
__device__ float4 g_p2[MAXBN];   // (x,y,z,|p|^2) xyz2
__device__ float  g_rL[MAXBN];
__device__ float  g_rR[MAXBN];
__device__ float  g_lgL[MAXBN];  // log2(ratioL)   (raw ratioL during level-0 sweep)
__device__ float  g_lgR[MAXBN];  // log2(ratioR)   (raw ratioR during level-0 sweep)
__device__ float  g_cost;

__device__ __forceinline__ float ex2f(float x) {
    float y; asm("ex2.approx.ftz.f32 %0, %1;" : "=f"(y) : "f"(x)); return y;
}
__device__ __forceinline__ float lg2f(float x) {
    float y; asm("lg2.approx.ftz.f32 %0, %1;" : "=f"(y) : "f"(x)); return y;
}
__device__ __forceinline__ float sqrtf_apx(float x) {
    float y; asm("sqrt.approx.ftz.f32 %0, %1;" : "=f"(y) : "f"(x)); return y;
}

// ---- packed f32x2 helpers (sm_103a) ----
__device__ __forceinline__ u64 pk2(float a, float b) {
    u64 r; asm("mov.b64 %0, {%1, %2};" : "=l"(r) : "f"(a), "f"(b)); return r;
}
__device__ __forceinline__ void upk2(float& a, float& b, u64 v) {
    asm("mov.b64 {%0, %1}, %2;" : "=f"(a), "=f"(b) : "l"(v));
}
__device__ __forceinline__ u64 f2fma(u64 a, u64 b, u64 c) {
    u64 d; asm("fma.rn.f32x2 %0, %1, %2, %3;" : "=l"(d) : "l"(a), "l"(b), "l"(c)); return d;
}
__device__ __forceinline__ u64 f2add(u64 a, u64 b) {
    u64 d; asm("add.rn.f32x2 %0, %1, %2;" : "=l"(d) : "l"(a), "l"(b)); return d;
}

#define UF_THRESH (-125.0f)   // ex2.ftz(x) == 0 exactly for x < -126

__global__ void setup_kernel(const float* __restrict__ x1, const float* __restrict__ x2,
                             float multiL, float multiR, int N, int total) {
    int idx = blockIdx.x * blockDim.x + threadIdx.x;
    if (idx >= total) return;
    int b = idx / N, i = idx - b * N;
    const float* p1 = x1 + (size_t)b * 3 * N + i;
    const float* p2 = x2 + (size_t)b * 3 * N + i;
    float a0 = p1[0], a1 = p1[N], a2 = p1[2 * N];
    g_p1[idx] = make_float4(a0, a1, a2, a0 * a0 + a1 * a1 + a2 * a2);
    float b0 = p2[0], b1 = p2[N], b2 = p2[2 * N];
    g_p2[idx] = make_float4(b0, b1, b2, b0 * b0 + b1 * b1 + b2 * b2);
    g_rL[idx] = multiL;
    g_rR[idx] = multiR;
    if (idx == 0) g_cost = 0.0f;
}

// MODE 1: rows = x1, cols = x2, fold_j = log2(remainR_j); epilogue writes lgL.
// MODE 2: rows = x2, cols = x1, fold_j = lgL_j;           epilogue updates remainR, writes lgR.
// arg(i,j) = klg*dist(i,j) + fold_j, accumulated via ex2.
template <int MODE, bool SPARSE>
__global__ void __launch_bounds__(128, 6) pass12_kernel(float klg, int N) {
    __shared__ ulonglong2 s_xy[TILE / 2];   // {x0x1, y0y1}
    __shared__ ulonglong2 s_zf[TILE / 2];   // {z0z1, fold'0 fold'1}  fold' = klg*|q|^2 + fold
    const int b = blockIdx.y, base = b * N;
    const int t = threadIdx.x, warp = t >> 5, lane = t & 31;
    const int r0 = blockIdx.x * ROWS_PER_BLOCK + warp * 4;

    const float4* P = (MODE == 1) ? g_p1 : g_p2;
    const float4* Q = (MODE == 1) ? g_p2 : g_p1;

    u64 rx[4], ry[4], rz[4], rw[4], acc[4];
#pragma unroll
    for (int r = 0; r < 4; r++) {
        float4 A = P[base + r0 + r];
        float kx = klg * -2.0f * A.x, ky = klg * -2.0f * A.y, kz = klg * -2.0f * A.z;
        float kw = klg * A.w;
        rx[r] = pk2(kx, kx); ry[r] = pk2(ky, ky); rz[r] = pk2(kz, kz); rw[r] = pk2(kw, kw);
        acc[r] = 0ull;
    }

    for (int c = 0; c < N; c += TILE) {
#pragma unroll
        for (int k = 0; k < TILE / 256; k++) {
            int p = t + k * 128;
            int j = base + c + 2 * p;
            float4 q0 = Q[j], q1 = Q[j + 1];
            float f0, f1;
            if (MODE == 1) { f0 = lg2f(g_rR[j]); f1 = lg2f(g_rR[j + 1]); }
            else           { f0 = g_lgL[j];      f1 = g_lgL[j + 1]; }
            f0 = fmaf(klg, q0.w, f0);
            f1 = fmaf(klg, q1.w, f1);
            ulonglong2 xy; xy.x = pk2(q0.x, q1.x); xy.y = pk2(q0.y, q1.y);
            ulonglong2 zf; zf.x = pk2(q0.z, q1.z); zf.y = pk2(f0, f1);
            s_xy[p] = xy; s_zf[p] = zf;
        }
        __syncthreads();
#pragma unroll 4
        for (int it = 0; it < TILE / 64; it++) {
            int p = it * 32 + lane;
            ulonglong2 xy = s_xy[p];
            ulonglong2 zf = s_zf[p];
            u64 a0 = f2fma(rz[0], zf.x, f2fma(ry[0], xy.y, f2fma(rx[0], xy.x, f2add(zf.y, rw[0]))));
            u64 a1 = f2fma(rz[1], zf.x, f2fma(ry[1], xy.y, f2fma(rx[1], xy.x, f2add(zf.y, rw[1]))));
            u64 a2 = f2fma(rz[2], zf.x, f2fma(ry[2], xy.y, f2fma(rx[2], xy.x, f2add(zf.y, rw[2]))));
            u64 a3 = f2fma(rz[3], zf.x, f2fma(ry[3], xy.y, f2fma(rx[3], xy.x, f2add(zf.y, rw[3]))));
            float e0, e1, e2, e3, e4, e5, e6, e7;
            upk2(e0, e1, a0); upk2(e2, e3, a1); upk2(e4, e5, a2); upk2(e6, e7, a3);
            if (SPARSE) {
                float m0 = fmaxf(fmaxf(e0, e1), fmaxf(e2, e3));
                float m1 = fmaxf(fmaxf(e4, e5), fmaxf(e6, e7));
                float mx = fmaxf(m0, m1);
                if (__all_sync(0xffffffffu, mx < UF_THRESH)) continue;
            }
            acc[0] = f2add(acc[0], pk2(ex2f(e0), ex2f(e1)));
            acc[1] = f2add(acc[1], pk2(ex2f(e2), ex2f(e3)));
            acc[2] = f2add(acc[2], pk2(ex2f(e4), ex2f(e5)));
            acc[3] = f2add(acc[3], pk2(ex2f(e6), ex2f(e7)));
        }
        __syncthreads();
    }

#pragma unroll
    for (int off = 16; off; off >>= 1) {
#pragma unroll
        for (int r = 0; r < 4; r++)
            acc[r] = f2add(acc[r], __shfl_down_sync(0xffffffffu, acc[r], off));
    }

    if (lane == 0) {
#pragma unroll
        for (int r = 0; r < 4; r++) {
            float lo, hi; upk2(lo, hi, acc[r]);
            float a = lo + hi;
            int idx = base + r0 + r;
            if (MODE == 1) {
                g_lgL[idx] = lg2f(g_rL[idx] / (EMD_EPS + a));
            } else {
                float rr   = g_rR[idx];
                float sumr = rr * a;
                float cons = fminf(rr / (sumr + EMD_EPS), 1.0f);
                g_lgR[idx] = lg2f(cons * rr);
                g_rR[idx]  = fmaxf(0.0f, rr - sumr);
            }
        }
    }
}

// P3: w = ex2(klg*d + lq_j) * ex2(lgL_i); remainL -= sum_j w; cost += w*sqrt(max(d,1e-20))
template <bool SPARSE>
__global__ void __launch_bounds__(128, 5) pass3_kernel(float klg, int N) {
    __shared__ ulonglong2 s_xy[TILE / 2];   // {x0x1, y0y1}
    __shared__ ulonglong2 s_zw[TILE / 2];   // {z0z1, |q|^2 pair}
    __shared__ u64        s_lq[TILE / 2];   // {lq0, lq1}
    const int b = blockIdx.y, base = b * N;
    const int t = threadIdx.x, warp = t >> 5, lane = t & 31;
    const int r0 = blockIdx.x * ROWS_PER_BLOCK + warp * 4;

    u64 rx[4], ry[4], rz[4], rw[4], wa[4], cs[4];
    float lgL[4];
#pragma unroll
    for (int r = 0; r < 4; r++) {
        float4 A = g_p1[base + r0 + r];
        rx[r] = pk2(-2.0f * A.x, -2.0f * A.x);
        ry[r] = pk2(-2.0f * A.y, -2.0f * A.y);
        rz[r] = pk2(-2.0f * A.z, -2.0f * A.z);
        rw[r] = pk2(A.w, A.w);
        lgL[r] = g_lgL[base + r0 + r];
        wa[r] = 0ull; cs[r] = 0ull;
    }
    const u64 klg2 = pk2(klg, klg);
    float th = 0.0f;
    if (SPARSE) {
        float lm = fmaxf(fmaxf(lgL[0], lgL[1]), fmaxf(lgL[2], lgL[3]));
        th = UF_THRESH - lm;   // skip chunk if all (klg*d + lq) < th
    }

    for (int c = 0; c < N; c += TILE) {
#pragma unroll
        for (int k = 0; k < TILE / 256; k++) {
            int p = t + k * 128;
            int j = base + c + 2 * p;
            float4 q0 = g_p2[j], q1 = g_p2[j + 1];
            ulonglong2 xy; xy.x = pk2(q0.x, q1.x); xy.y = pk2(q0.y, q1.y);
            ulonglong2 zw; zw.x = pk2(q0.z, q1.z); zw.y = pk2(q0.w, q1.w);
            s_xy[p] = xy; s_zw[p] = zw;
            s_lq[p] = pk2(g_lgR[j], g_lgR[j + 1]);
        }
        __syncthreads();
#pragma unroll 4
        for (int it = 0; it < TILE / 64; it++) {
            int p = it * 32 + lane;
            ulonglong2 xy = s_xy[p];
            ulonglong2 zw = s_zw[p];
            u64 lq2 = s_lq[p];
            u64 d0 = f2fma(rz[0], zw.x, f2fma(ry[0], xy.y, f2fma(rx[0], xy.x, f2add(zw.y, rw[0]))));
            u64 d1 = f2fma(rz[1], zw.x, f2fma(ry[1], xy.y, f2fma(rx[1], xy.x, f2add(zw.y, rw[1]))));
            u64 d2 = f2fma(rz[2], zw.x, f2fma(ry[2], xy.y, f2fma(rx[2], xy.x, f2add(zw.y, rw[2]))));
            u64 d3 = f2fma(rz[3], zw.x, f2fma(ry[3], xy.y, f2fma(rx[3], xy.x, f2add(zw.y, rw[3]))));
            u64 a0 = f2fma(klg2, d0, lq2);
            u64 a1 = f2fma(klg2, d1, lq2);
            u64 a2 = f2fma(klg2, d2, lq2);
            u64 a3 = f2fma(klg2, d3, lq2);
            float f0, f1, f2v, f3v, f4, f5, f6, f7;
            upk2(f0, f1, a0); upk2(f2v, f3v, a1); upk2(f4, f5, a2); upk2(f6, f7, a3);
            if (SPARSE) {
                float m0 = fmaxf(fmaxf(f0, f1), fmaxf(f2v, f3v));
                float m1 = fmaxf(fmaxf(f4, f5), fmaxf(f6, f7));
                float mx = fmaxf(m0, m1);
                if (__all_sync(0xffffffffu, mx < th)) continue;
            }
#pragma unroll
            for (int r = 0; r < 4; r++) {
                u64 dd = (r == 0) ? d0 : (r == 1) ? d1 : (r == 2) ? d2 : d3;
                float av0, av1;
                if (r == 0) { av0 = f0; av1 = f1; }
                else if (r == 1) { av0 = f2v; av1 = f3v; }
                else if (r == 2) { av0 = f4; av1 = f5; }
                else { av0 = f6; av1 = f7; }
                float dl, dh; upk2(dl, dh, dd);
                float c0 = fmaxf(dl, 1e-20f), c1 = fmaxf(dh, 1e-20f);
                float w0 = ex2f(av0), w1 = ex2f(av1);
                float s0 = sqrtf_apx(c0), s1 = sqrtf_apx(c1);
                u64 wv = pk2(w0, w1);
                wa[r] = f2add(wa[r], wv);
                cs[r] = f2fma(wv, pk2(s0, s1), cs[r]);
            }
        }
        __syncthreads();
    }

#pragma unroll
    for (int off = 16; off; off >>= 1) {
#pragma unroll
        for (int r = 0; r < 4; r++) {
            wa[r] = f2add(wa[r], __shfl_down_sync(0xffffffffu, wa[r], off));
            cs[r] = f2add(cs[r], __shfl_down_sync(0xffffffffu, cs[r], off));
        }
    }
    if (lane == 0) {
        float cost = 0.0f;
#pragma unroll
        for (int r = 0; r < 4; r++) {
            int idx = base + r0 + r;
            float eL = ex2f(lgL[r]);   // ratioL
            float wl, wh; upk2(wl, wh, wa[r]);
            float cl, ch; upk2(cl, ch, cs[r]);
            g_rL[idx] = fmaxf(0.0f, g_rL[idx] - eL * (wl + wh));
            cost = fmaf(eL, cl + ch, cost);
        }
        atomicAdd(&g_cost, cost);
    }
}

// ---- level == 0 sweep (e == 1 everywhere): exact O(N) prep + sqrt-only pairwise cost ----
__global__ void level0_prep(int N) {
    __shared__ float red[256];
    __shared__ float Tv, Uv;
    const int b = blockIdx.x, base = b * N, t = threadIdx.x;
    float ts = 0.0f, us = 0.0f;
    for (int i = t; i < N; i += 256) { ts += g_rR[base + i]; us += g_rL[base + i]; }
    red[t] = ts; __syncthreads();
    for (int o = 128; o; o >>= 1) { if (t < o) red[t] += red[t + o]; __syncthreads(); }
    if (t == 0) Tv = red[0];
    __syncthreads();
    red[t] = us; __syncthreads();
    for (int o = 128; o; o >>= 1) { if (t < o) red[t] += red[t + o]; __syncthreads(); }
    if (t == 0) Uv = red[0];
    __syncthreads();
    float scale = 1.0f / (EMD_EPS + Tv);   // ratioL_i = rL_i * scale
    float S = Uv * scale;                  // sum_i ratioL_i
    for (int i = t; i < N; i += 256) {
        g_lgL[base + i] = g_rL[base + i] * scale;    // raw ratioL
        float rr   = g_rR[base + i];
        float sumr = rr * S;
        float cons = fminf(rr / (sumr + EMD_EPS), 1.0f);
        g_lgR[base + i] = cons * rr;                 // raw ratioR
    }
}

__global__ void __launch_bounds__(128, 6) level0_cost(int N) {
    __shared__ ulonglong2 s_xy[TILE / 2];
    __shared__ ulonglong2 s_zw[TILE / 2];
    __shared__ u64        s_rr[TILE / 2];   // {ratioR0, ratioR1}
    const int b = blockIdx.y, base = b * N;
    const int t = threadIdx.x, warp = t >> 5, lane = t & 31;
    const int r0 = blockIdx.x * ROWS_PER_BLOCK + warp * 4;

    u64 rx[4], ry[4], rz[4], rw[4], cs[4];
    float rl[4];
#pragma unroll
    for (int r = 0; r < 4; r++) {
        float4 A = g_p1[base + r0 + r];
        rx[r] = pk2(-2.0f * A.x, -2.0f * A.x);
        ry[r] = pk2(-2.0f * A.y, -2.0f * A.y);
        rz[r] = pk2(-2.0f * A.z, -2.0f * A.z);
        rw[r] = pk2(A.w, A.w);
        rl[r] = g_lgL[base + r0 + r];   // raw ratioL
        cs[r] = 0ull;
    }

    for (int c = 0; c < N; c += TILE) {
#pragma unroll
        for (int k = 0; k < TILE / 256; k++) {
            int p = t + k * 128;
            int j = base + c + 2 * p;
            float4 q0 = g_p2[j], q1 = g_p2[j + 1];
            ulonglong2 xy; xy.x = pk2(q0.x, q1.x); xy.y = pk2(q0.y, q1.y);
            ulonglong2 zw; zw.x = pk2(q0.z, q1.z); zw.y = pk2(q0.w, q1.w);
            s_xy[p] = xy; s_zw[p] = zw;
            s_rr[p] = pk2(g_lgR[j], g_lgR[j + 1]);   // raw ratioR
        }
        __syncthreads();
#pragma unroll 4
        for (int it = 0; it < TILE / 64; it++) {
            int p = it * 32 + lane;
            ulonglong2 xy = s_xy[p];
            ulonglong2 zw = s_zw[p];
            u64 rr2 = s_rr[p];
#pragma unroll
            for (int r = 0; r < 4; r++) {
                u64 dd = f2fma(rz[r], zw.x, f2fma(ry[r], xy.y, f2fma(rx[r], xy.x, f2add(zw.y, rw[r]))));
                float dl, dh; upk2(dl, dh, dd);
                float s0 = sqrtf_apx(fmaxf(dl, 1e-20f));
                float s1 = sqrtf_apx(fmaxf(dh, 1e-20f));
                cs[r] = f2fma(rr2, pk2(s0, s1), cs[r]);
            }
        }
        __syncthreads();
    }

#pragma unroll
    for (int off = 16; off; off >>= 1) {
#pragma unroll
        for (int r = 0; r < 4; r++)
            cs[r] = f2add(cs[r], __shfl_down_sync(0xffffffffu, cs[r], off));
    }
    if (lane == 0) {
        float cost = 0.0f;
#pragma unroll
        for (int r = 0; r < 4; r++) {
            float cl, ch; upk2(cl, ch, cs[r]);
            cost = fmaf(rl[r], cl + ch, cost);
        }
        atomicAdd(&g_cost, cost);
    }
}

__global__ void final_kernel(float* out, float inv) {
    out[0] = g_cost * inv;
}

extern "C" void kernel_launch(void* const* d_in, const int* in_sizes, int n_in,
                              void* d_out, int out_size) {
    const float* x1 = (const float*)d_in[0];
    const float* x2 = (const float*)d_in[1];
    const int B = 4;
    const int N = in_sizes[0] / (3 * B);   // 4096
    const int n = N, m = N;

    float multiL, multiR;
    if (n >= m) { multiL = 1.0f; multiR = (float)(n / m); }
    else        { multiL = (float)(m / n); multiR = 1.0f; }

    int total = B * N;
    setup_kernel<<<(total + 255) / 256, 256>>>(x1, x2, multiL, multiR, N, total);

    dim3 grid(N / ROWS_PER_BLOCK, B);
    const float LOG2E = 1.4426950408889634f;
    for (int s = 0; s < 9; s++) {
        float level = -ldexpf(1.0f, 2 * (7 - s));   // -4^(7-s); s=8 -> -0.25
        float klg = level * LOG2E;
        if (s <= 4) {
            pass12_kernel<1, true><<<grid, 128>>>(klg, N);
            pass12_kernel<2, true><<<grid, 128>>>(klg, N);
            pass3_kernel<true><<<grid, 128>>>(klg, N);
        } else {
            pass12_kernel<1, false><<<grid, 128>>>(klg, N);
            pass12_kernel<2, false><<<grid, 128>>>(klg, N);
            pass3_kernel<false><<<grid, 128>>>(klg, N);
        }
    }
    // level == 0 sweep: exact closed-form ratios + sqrt-only pairwise cost
    level0_prep<<<B, 256>>>(N);
    level0_cost<<<grid, 128>>>(N);

    float mn = (float)((n < m ? n : m) * B);
    final_kernel<<<1, 1>>>((float*)d_out, 1.0f / mn);
}